// round 9
// baseline (speedup 1.0000x reference)
#include <cuda_runtime.h>
#include <cuda_bf16.h>
#include <math.h>

// ---------------------------------------------------------------------------
// Problem dims
// ---------------------------------------------------------------------------
#define VB   64            // batch
#define TT   512           // seq len
#define UU   256           // hidden per direction
#define GGN  768           // 3*U
#define MM   (VB*TT)       // 32768 projection rows
#define CC   20            // classes

// ---------------------------------------------------------------------------
// Scratch (device globals; allocation is forbidden)
// ---------------------------------------------------------------------------
__device__ float g_xw[2][MM][GGN];    // input projections per direction
__device__ float g_h1[VB][TT][2*UU];  // layer-1 output, concat(fwd | bwd)
__device__ float g_h2[VB][2*UU];      // layer-2 final states

// ---------------------------------------------------------------------------
// Helpers
// ---------------------------------------------------------------------------
typedef unsigned long long u64;

__device__ __forceinline__ u64 pack2(float a, float b) {
    u64 r; asm("mov.b64 %0, {%1,%2};" : "=l"(r) : "f"(a), "f"(b)); return r;
}
__device__ __forceinline__ void fma2(u64& d, u64 a, u64 b) {
    asm("fma.rn.f32x2 %0, %1, %2, %0;" : "+l"(d) : "l"(a), "l"(b));
}
__device__ __forceinline__ u64 add2(u64 a, u64 b) {
    u64 r; asm("add.rn.f32x2 %0, %1, %2;" : "=l"(r) : "l"(a), "l"(b)); return r;
}
__device__ __forceinline__ float lohi_sum(u64 v) {
    unsigned lo, hi; asm("mov.b64 {%0,%1}, %2;" : "=r"(lo), "=r"(hi) : "l"(v));
    return __uint_as_float(lo) + __uint_as_float(hi);
}
__device__ __forceinline__ void unpack2(u64 v, float& a, float& b) {
    unsigned lo, hi; asm("mov.b64 {%0,%1}, %2;" : "=r"(lo), "=r"(hi) : "l"(v));
    a = __uint_as_float(lo); b = __uint_as_float(hi);
}
__device__ __forceinline__ u64 shflx64(u64 v, int m) {
    unsigned lo = (unsigned)v, hi = (unsigned)(v >> 32);
    lo = __shfl_xor_sync(0xffffffffu, lo, m);
    hi = __shfl_xor_sync(0xffffffffu, hi, m);
    return ((u64)hi << 32) | (u64)lo;
}
__device__ __forceinline__ unsigned smem_u32(const void* p) {
    unsigned a;
    asm("{ .reg .u64 t; cvta.to.shared.u64 t, %1; cvt.u32.u64 %0, t; }" : "=r"(a) : "l"(p));
    return a;
}
__device__ __forceinline__ unsigned mapa_u32(unsigned addr, int rank) {
    unsigned r;
    asm("mapa.shared::cluster.u32 %0, %1, %2;" : "=r"(r) : "r"(addr), "r"(rank));
    return r;
}
__device__ __forceinline__ void st_cluster_f32(unsigned addr, float v) {
    asm volatile("st.shared::cluster.f32 [%0], %1;" :: "r"(addr), "f"(v) : "memory");
}
__device__ __forceinline__ void cluster_sync_() {
    asm volatile("barrier.cluster.arrive.aligned;" ::: "memory");
    asm volatile("barrier.cluster.wait.aligned;"   ::: "memory");
}
__device__ __forceinline__ float fast_sigmoid(float x) {
    return 1.f / (1.f + __expf(-x));
}
__device__ __forceinline__ float fast_tanh(float x) {
    x = fminf(fmaxf(x, -15.f), 15.f);
    float t = __expf(-2.f * x);
    return (1.f - t) / (1.f + t);
}

// ---------------------------------------------------------------------------
// Projection GEMM: g_xw[dir][m][g] = A[m][:] @ W[:][g] + b0[g]
//   gather==1 (layer 1): A row m = emb[x[m]], K=300
//   gather==0 (layer 2): A row m = g_h1 flat [m][512], K=512
// 128x128 tiles, BK=8, 256 threads, 8x8 microtile with fma.rn.f32x2.
// ---------------------------------------------------------------------------
__global__ __launch_bounds__(256, 2) void proj_kernel(
    const float* __restrict__ emb, const int* __restrict__ xi,
    const float* __restrict__ Wf, const float* __restrict__ Wb,
    const float* __restrict__ bf, const float* __restrict__ bb,
    int K, int gather)
{
    const int dir = blockIdx.z;
    const float* Wm   = dir ? Wb : Wf;
    const float* bias = dir ? bb : bf;   // row 0 of [2,G]
    float* Out = &g_xw[dir][0][0];

    __shared__ float As[8][128];
    __shared__ float Bs[8][128];

    const int tid = threadIdx.x;
    const int m0 = blockIdx.x * 128;
    const int n0 = blockIdx.y * 128;
    const int tx = tid & 15, ty = tid >> 4;

    u64 acc[8][4];
#pragma unroll
    for (int i = 0; i < 8; i++)
#pragma unroll
        for (int j = 0; j < 4; j++) acc[i][j] = 0ull;

    // A loader: 2 threads per row, one float4 each (K is a multiple of 4)
    const int lm = tid >> 1;
    const int kpart = (tid & 1) * 4;
    const float* Arow;
    if (gather) Arow = emb + (size_t)xi[m0 + lm] * K;
    else        Arow = &g_h1[0][0][0] + (size_t)(m0 + lm) * K;

    // B loader: one float4 per thread
    const int bkk = tid >> 5;
    const int bn  = (tid & 31) * 4;

    const int ktiles = (K + 7) / 8;
    for (int kt = 0; kt < ktiles; ++kt) {
        const int k0 = kt * 8;
        {
            int k = k0 + kpart;
            float4 av = make_float4(0.f, 0.f, 0.f, 0.f);
            if (k < K) av = *(const float4*)(Arow + k);
            As[kpart + 0][lm] = av.x;
            As[kpart + 1][lm] = av.y;
            As[kpart + 2][lm] = av.z;
            As[kpart + 3][lm] = av.w;
        }
        {
            int k = k0 + bkk;
            float4 v = make_float4(0.f, 0.f, 0.f, 0.f);
            if (k < K) v = *(const float4*)(Wm + (size_t)k * GGN + n0 + bn);
            *(float4*)&Bs[bkk][bn] = v;
        }
        __syncthreads();
#pragma unroll
        for (int kk = 0; kk < 8; ++kk) {
            float a[8];
            *(float4*)&a[0] = *(const float4*)&As[kk][ty * 8];
            *(float4*)&a[4] = *(const float4*)&As[kk][ty * 8 + 4];
            float4 b0 = *(const float4*)&Bs[kk][tx * 8];
            float4 b1 = *(const float4*)&Bs[kk][tx * 8 + 4];
            u64 bp[4];
            bp[0] = pack2(b0.x, b0.y); bp[1] = pack2(b0.z, b0.w);
            bp[2] = pack2(b1.x, b1.y); bp[3] = pack2(b1.z, b1.w);
#pragma unroll
            for (int i = 0; i < 8; i++) {
                u64 as = pack2(a[i], a[i]);
#pragma unroll
                for (int j = 0; j < 4; j++) fma2(acc[i][j], as, bp[j]);
            }
        }
        __syncthreads();
    }

#pragma unroll
    for (int i = 0; i < 8; i++) {
        const int m = m0 + ty * 8 + i;
        float* orow = Out + (size_t)m * GGN + n0 + tx * 8;
#pragma unroll
        for (int j = 0; j < 2; j++) {
            float v0, v1, v2, v3;
            unpack2(acc[i][2 * j + 0], v0, v1);
            unpack2(acc[i][2 * j + 1], v2, v3);
            float4 v;
            v.x = v0 + bias[n0 + tx * 8 + j * 4 + 0];
            v.y = v1 + bias[n0 + tx * 8 + j * 4 + 1];
            v.z = v2 + bias[n0 + tx * 8 + j * 4 + 2];
            v.w = v3 + bias[n0 + tx * 8 + j * 4 + 3];
            *(float4*)(orow + j * 4) = v;
        }
    }
}

// ---------------------------------------------------------------------------
// Recurrence v2. Grid: 128 CTAs as 16 clusters of 8, 512 threads/CTA.
//   cluster c: dir = c>>3, batch-group bg = c&7 (8 batch elems)
//   CTA rank r owns hidden units [r*32, r*32+32)
// Thread (kg = tid&15, ul = tid>>4):
//   unit ug = rank*32 + ul; k-slice pairs {2*kg + 32*i | i=0..7} (16 k-values)
//   weights register-stationary: 24 u64 (3 gates x 8 k-pairs)
//   two passes of 4 batches each; shfl-fold over 16 kg lanes; thread ends
//   with full sums for b_loc = (kg>>2)&3 (4-way duplicated), carries h_prev
//   in registers, broadcasts new h to 2 of the 8 CTAs (duplicates cover all).
//   xw for the NEXT step prefetched at loop top. One cluster.sync per step.
// ---------------------------------------------------------------------------
__global__ void __cluster_dims__(8, 1, 1) __launch_bounds__(512, 1)
rec_kernel(const float* __restrict__ rkf, const float* __restrict__ rkb,
           const float* __restrict__ biasf, const float* __restrict__ biasb,
           int layer)
{
    __shared__ float hs[2][8][UU];   // [buffer][batch-in-group][unit], 16KB

    const int cta  = blockIdx.x;
    const int rank = cta & 7;
    const int cl   = cta >> 3;
    const int dir  = cl >> 3;
    const int bg   = cl & 7;

    const float* rk   = dir ? rkb   : rkf;
    const float* bias = dir ? biasb : biasf;
    const float* xw   = &g_xw[dir][0][0];

    const int tid = threadIdx.x;
    const int kg  = tid & 15;
    const int ul  = tid >> 4;            // 0..31
    const int ug  = rank * 32 + ul;
    const int bl  = (kg >> 2) & 3;       // fold output batch (pass-local)
    const int b0g = bg * 8 + bl;         // pass-0 global batch
    const int b1g = b0g + 4;             // pass-1 global batch

    // ---- recurrent weights in registers (3 gates x 8 k-pairs) ----
    u64 rz[8], rr[8], rh[8];
#pragma unroll
    for (int i = 0; i < 8; i++) {
        const int k = 2 * kg + 32 * i;
        rz[i] = pack2(rk[(size_t)k * GGN + ug],            rk[(size_t)(k + 1) * GGN + ug]);
        rr[i] = pack2(rk[(size_t)k * GGN + UU + ug],       rk[(size_t)(k + 1) * GGN + UU + ug]);
        rh[i] = pack2(rk[(size_t)k * GGN + 2 * UU + ug],   rk[(size_t)(k + 1) * GGN + 2 * UU + ug]);
    }
    const float rbz = bias[GGN + ug];
    const float rbr = bias[GGN + UU + ug];
    const float rbh = bias[GGN + 2 * UU + ug];

    for (int i = tid; i < 2 * 8 * UU; i += 512) ((float*)hs)[i] = 0.f;
    cluster_sync_();   // zeroed cluster-wide before step 0

    // ---- precomputed remote-store addresses (buffer 0; add parity*8192) ----
    const unsigned hbase = smem_u32(hs);
    unsigned dsta[2][2];
#pragma unroll
    for (int q = 0; q < 2; q++) {
        unsigned local = hbase + (unsigned)(((q * 4 + bl) * UU + ug) * 4);
#pragma unroll
        for (int r = 0; r < 2; r++)
            dsta[q][r] = mapa_u32(local, 2 * (kg & 3) + r);
    }

    const float* xr0 = xw + (size_t)b0g * TT * GGN;
    const float* xr1 = xw + (size_t)b1g * TT * GGN;

    // prime current-step xw
    int t0 = dir ? TT - 1 : 0;
    float cx[2][3];
    cx[0][0] = xr0[(size_t)t0 * GGN + ug];
    cx[0][1] = xr0[(size_t)t0 * GGN + UU + ug];
    cx[0][2] = xr0[(size_t)t0 * GGN + 2 * UU + ug];
    cx[1][0] = xr1[(size_t)t0 * GGN + ug];
    cx[1][1] = xr1[(size_t)t0 * GGN + UU + ug];
    cx[1][2] = xr1[(size_t)t0 * GGN + 2 * UU + ug];

    float hq[2] = {0.f, 0.f};   // carried h_prev for (b0g,ug) and (b1g,ug)
    const bool wlane = (kg & 3) == 0;

    int p = 0;
    for (int s = 0; s < TT; ++s) {
        const int t = dir ? (TT - 1 - s) : s;

        // prefetch next-step xw (clamped; last iter loads are discarded)
        int tn = dir ? (TT - 2 - s) : (s + 1);
        tn = tn < 0 ? 0 : (tn >= TT ? TT - 1 : tn);
        float nx[2][3];
        nx[0][0] = xr0[(size_t)tn * GGN + ug];
        nx[0][1] = xr0[(size_t)tn * GGN + UU + ug];
        nx[0][2] = xr0[(size_t)tn * GGN + 2 * UU + ug];
        nx[1][0] = xr1[(size_t)tn * GGN + ug];
        nx[1][1] = xr1[(size_t)tn * GGN + UU + ug];
        nx[1][2] = xr1[(size_t)tn * GGN + 2 * UU + ug];

        const float* hc = (const float*)((const char*)hs + p * 8192);
        float hnq[2];

#pragma unroll
        for (int q = 0; q < 2; ++q) {
            u64 az[4], ar4[4], ah4[4];
#pragma unroll
            for (int b = 0; b < 4; b++) { az[b] = 0ull; ar4[b] = 0ull; ah4[b] = 0ull; }

#pragma unroll
            for (int i = 0; i < 8; i++) {
#pragma unroll
                for (int b = 0; b < 4; b++) {
                    u64 hp = *(const u64*)(hc + (q * 4 + b) * UU + 2 * kg + 32 * i);
                    fma2(az[b],  rz[i], hp);
                    fma2(ar4[b], rr[i], hp);
                    fma2(ah4[b], rh[i], hp);
                }
            }

            // fold over 16 kg lanes: 4 accs -> 1, then duplicate-sum
            {
                const bool up8 = (kg & 8) != 0;
#pragma unroll
                for (int j = 0; j < 2; j++) {
                    const int keep = up8 ? 2 + j : j;
                    const int send = up8 ? j : 2 + j;
                    az[j]  = add2(az[keep],  shflx64(az[send],  8));
                    ar4[j] = add2(ar4[keep], shflx64(ar4[send], 8));
                    ah4[j] = add2(ah4[keep], shflx64(ah4[send], 8));
                }
                const bool up4 = (kg & 4) != 0;
                const int keep = up4 ? 1 : 0;
                const int send = up4 ? 0 : 1;
                az[0]  = add2(az[keep],  shflx64(az[send],  4));
                ar4[0] = add2(ar4[keep], shflx64(ar4[send], 4));
                ah4[0] = add2(ah4[keep], shflx64(ah4[send], 4));
                az[0]  = add2(az[0],  shflx64(az[0],  2));
                ar4[0] = add2(ar4[0], shflx64(ar4[0], 2));
                ah4[0] = add2(ah4[0], shflx64(ah4[0], 2));
                az[0]  = add2(az[0],  shflx64(az[0],  1));
                ar4[0] = add2(ar4[0], shflx64(ar4[0], 1));
                ah4[0] = add2(ah4[0], shflx64(ah4[0], 1));
            }

            const float rzs  = lohi_sum(az[0])  + rbz;
            const float rrs  = lohi_sum(ar4[0]) + rbr;
            const float rhs_ = lohi_sum(ah4[0]) + rbh;

            const float z  = fast_sigmoid(cx[q][0] + rzs);
            const float r  = fast_sigmoid(cx[q][1] + rrs);
            const float hh = fast_tanh(cx[q][2] + r * rhs_);
            const float hn = z * hq[q] + (1.f - z) * hh;
            hnq[q] = hn;
            hq[q]  = hn;
        }

        // broadcast new h: 4 duplicate lanes x 2 ranks each cover all 8 CTAs
        const unsigned boff = (unsigned)((p ^ 1) * 8192);
        st_cluster_f32(dsta[0][0] + boff, hnq[0]);
        st_cluster_f32(dsta[0][1] + boff, hnq[0]);
        st_cluster_f32(dsta[1][0] + boff, hnq[1]);
        st_cluster_f32(dsta[1][1] + boff, hnq[1]);

        if (layer == 1) {
            if (wlane) {
                g_h1[b0g][t][dir * UU + ug] = hnq[0];
                g_h1[b1g][t][dir * UU + ug] = hnq[1];
            }
        } else if (s == TT - 1) {
            if (wlane) {
                g_h2[b0g][dir * UU + ug] = hnq[0];
                g_h2[b1g][dir * UU + ug] = hnq[1];
            }
        }

        cluster_sync_();

#pragma unroll
        for (int q = 0; q < 2; q++)
#pragma unroll
            for (int g = 0; g < 3; g++) cx[q][g] = nx[q][g];
        p ^= 1;
    }
}

// ---------------------------------------------------------------------------
// Output: softmax(g_h2 @ wout + bout). 64 blocks x 32 threads.
// ---------------------------------------------------------------------------
__global__ __launch_bounds__(32) void out_kernel(
    const float* __restrict__ wout, const float* __restrict__ bout,
    float* __restrict__ out)
{
    __shared__ float h[2 * UU];
    __shared__ float sv[32];
    const int b = blockIdx.x, tid = threadIdx.x;

    for (int i = tid; i < 2 * UU; i += 32) h[i] = g_h2[b][i];
    __syncthreads();

    float s = 0.f;
    if (tid < CC) {
        for (int k = 0; k < 2 * UU; k++) s += h[k] * wout[(size_t)k * CC + tid];
        s += bout[tid];
    }
    sv[tid] = (tid < CC) ? s : -1e30f;
    __syncthreads();

    if (tid < CC) {
        float mx = -1e30f;
        for (int j = 0; j < CC; j++) mx = fmaxf(mx, sv[j]);
        float sum = 0.f;
        for (int j = 0; j < CC; j++) sum += expf(sv[j] - mx);
        out[b * CC + tid] = expf(s - mx) / sum;
    }
}

// ---------------------------------------------------------------------------
// Launch
// ---------------------------------------------------------------------------
extern "C" void kernel_launch(void* const* d_in, const int* in_sizes, int n_in,
                              void* d_out, int out_size) {
    (void)in_sizes; (void)n_in; (void)out_size;
    const int*   x    = (const int*)  d_in[0];
    const float* emb  = (const float*)d_in[1];
    const float* k1f  = (const float*)d_in[2];
    const float* rk1f = (const float*)d_in[3];
    const float* b1f  = (const float*)d_in[4];
    const float* k1b  = (const float*)d_in[5];
    const float* rk1b = (const float*)d_in[6];
    const float* b1b  = (const float*)d_in[7];
    const float* k2f  = (const float*)d_in[8];
    const float* rk2f = (const float*)d_in[9];
    const float* b2f  = (const float*)d_in[10];
    const float* k2b  = (const float*)d_in[11];
    const float* rk2b = (const float*)d_in[12];
    const float* b2b  = (const float*)d_in[13];
    const float* wout = (const float*)d_in[14];
    const float* bout = (const float*)d_in[15];
    float* out = (float*)d_out;

    dim3 pgrid(MM / 128, GGN / 128, 2);

    // Layer 1: input projections from embeddings, then bidirectional scan
    proj_kernel<<<pgrid, 256>>>(emb, x, k1f, k1b, b1f, b1b, 300, 1);
    rec_kernel<<<128, 512>>>(rk1f, rk1b, b1f, b1b, 1);

    // Layer 2: projections from h1, then bidirectional scan (final states only)
    proj_kernel<<<pgrid, 256>>>(emb, x, k2f, k2b, b2f, b2b, 2 * UU, 0);
    rec_kernel<<<128, 512>>>(rk2f, rk2b, b2f, b2b, 2);

    out_kernel<<<VB, 32>>>(wout, bout, out);
}

// round 13
// speedup vs baseline: 1.0451x; 1.0451x over previous
#include <cuda_runtime.h>
#include <cuda_bf16.h>
#include <math.h>

// ---------------------------------------------------------------------------
// Problem dims
// ---------------------------------------------------------------------------
#define VB   64            // batch
#define TT   512           // seq len
#define UU   256           // hidden per direction
#define GGN  768           // 3*U
#define MM   (VB*TT)       // 32768 projection rows
#define CC   20            // classes

// ---------------------------------------------------------------------------
// Scratch (device globals; allocation is forbidden)
// ---------------------------------------------------------------------------
__device__ float g_xw[2][MM][GGN];    // input projections per direction
__device__ float g_h1[VB][TT][2*UU];  // layer-1 output, concat(fwd | bwd)
__device__ float g_h2[VB][2*UU];      // layer-2 final states

// ---------------------------------------------------------------------------
// Helpers
// ---------------------------------------------------------------------------
typedef unsigned long long u64;

__device__ __forceinline__ u64 pack2(float a, float b) {
    u64 r; asm("mov.b64 %0, {%1,%2};" : "=l"(r) : "f"(a), "f"(b)); return r;
}
__device__ __forceinline__ void fma2(u64& d, u64 a, u64 b) {
    asm("fma.rn.f32x2 %0, %1, %2, %0;" : "+l"(d) : "l"(a), "l"(b));
}
__device__ __forceinline__ u64 add2(u64 a, u64 b) {
    u64 r; asm("add.rn.f32x2 %0, %1, %2;" : "=l"(r) : "l"(a), "l"(b)); return r;
}
__device__ __forceinline__ float lohi_sum(u64 v) {
    unsigned lo, hi; asm("mov.b64 {%0,%1}, %2;" : "=r"(lo), "=r"(hi) : "l"(v));
    return __uint_as_float(lo) + __uint_as_float(hi);
}
__device__ __forceinline__ void unpack2(u64 v, float& a, float& b) {
    unsigned lo, hi; asm("mov.b64 {%0,%1}, %2;" : "=r"(lo), "=r"(hi) : "l"(v));
    a = __uint_as_float(lo); b = __uint_as_float(hi);
}
__device__ __forceinline__ u64 shflx64(u64 v, int m) {
    unsigned lo = (unsigned)v, hi = (unsigned)(v >> 32);
    lo = __shfl_xor_sync(0xffffffffu, lo, m);
    hi = __shfl_xor_sync(0xffffffffu, hi, m);
    return ((u64)hi << 32) | (u64)lo;
}
__device__ __forceinline__ unsigned smem_u32(const void* p) {
    unsigned a;
    asm("{ .reg .u64 t; cvta.to.shared.u64 t, %1; cvt.u32.u64 %0, t; }" : "=r"(a) : "l"(p));
    return a;
}
__device__ __forceinline__ unsigned mapa_u32(unsigned addr, int rank) {
    unsigned r;
    asm("mapa.shared::cluster.u32 %0, %1, %2;" : "=r"(r) : "r"(addr), "r"(rank));
    return r;
}
__device__ __forceinline__ void cluster_sync_() {
    asm volatile("barrier.cluster.arrive.aligned;" ::: "memory");
    asm volatile("barrier.cluster.wait.aligned;"   ::: "memory");
}
// Remote store that signals the DEST CTA's mbarrier with 4 tx bytes.
__device__ __forceinline__ void st_async_f32(unsigned daddr, float v, unsigned mbaddr) {
    asm volatile(
        "st.async.weak.shared::cluster.mbarrier::complete_tx::bytes.b32 [%0], %1, [%2];"
        :: "r"(daddr), "r"(__float_as_uint(v)), "r"(mbaddr) : "memory");
}
__device__ __forceinline__ void mbar_init(unsigned addr, unsigned cnt) {
    asm volatile("mbarrier.init.shared.b64 [%0], %1;" :: "r"(addr), "r"(cnt) : "memory");
}
__device__ __forceinline__ void mbar_expect_tx(unsigned addr, unsigned bytes) {
    asm volatile("mbarrier.arrive.expect_tx.shared.b64 _, [%0], %1;"
                 :: "r"(addr), "r"(bytes) : "memory");
}
__device__ __forceinline__ void mbar_wait_cluster(unsigned addr, int parity) {
    asm volatile(
        "{\n\t.reg .pred P;\n\t"
        "LW_%=:\n\t"
        "mbarrier.try_wait.parity.acquire.cluster.shared::cta.b64 P, [%0], %1, 0x989680;\n\t"
        "@P bra.uni LD_%=;\n\t"
        "bra.uni LW_%=;\n\t"
        "LD_%=:\n\t}"
        :: "r"(addr), "r"(parity) : "memory");
}
__device__ __forceinline__ float fast_sigmoid(float x) {
    return 1.f / (1.f + __expf(-x));
}
__device__ __forceinline__ float fast_tanh(float x) {
    x = fminf(fmaxf(x, -15.f), 15.f);
    float t = __expf(-2.f * x);
    return (1.f - t) / (1.f + t);
}

// ---------------------------------------------------------------------------
// Projection GEMM: g_xw[dir][m][g] = A[m][:] @ W[:][g] + b0[g]
//   gather==1 (layer 1): A row m = emb[x[m]], K=300
//   gather==0 (layer 2): A row m = g_h1 flat [m][512], K=512
// 128x128 tiles, BK=8, 256 threads, 8x8 microtile with fma.rn.f32x2.
// ---------------------------------------------------------------------------
__global__ __launch_bounds__(256, 2) void proj_kernel(
    const float* __restrict__ emb, const int* __restrict__ xi,
    const float* __restrict__ Wf, const float* __restrict__ Wb,
    const float* __restrict__ bf, const float* __restrict__ bb,
    int K, int gather)
{
    const int dir = blockIdx.z;
    const float* Wm   = dir ? Wb : Wf;
    const float* bias = dir ? bb : bf;   // row 0 of [2,G]
    float* Out = &g_xw[dir][0][0];

    __shared__ float As[8][128];
    __shared__ float Bs[8][128];

    const int tid = threadIdx.x;
    const int m0 = blockIdx.x * 128;
    const int n0 = blockIdx.y * 128;
    const int tx = tid & 15, ty = tid >> 4;

    u64 acc[8][4];
#pragma unroll
    for (int i = 0; i < 8; i++)
#pragma unroll
        for (int j = 0; j < 4; j++) acc[i][j] = 0ull;

    const int lm = tid >> 1;
    const int kpart = (tid & 1) * 4;
    const float* Arow;
    if (gather) Arow = emb + (size_t)xi[m0 + lm] * K;
    else        Arow = &g_h1[0][0][0] + (size_t)(m0 + lm) * K;

    const int bkk = tid >> 5;
    const int bn  = (tid & 31) * 4;

    const int ktiles = (K + 7) / 8;
    for (int kt = 0; kt < ktiles; ++kt) {
        const int k0 = kt * 8;
        {
            int k = k0 + kpart;
            float4 av = make_float4(0.f, 0.f, 0.f, 0.f);
            if (k < K) av = *(const float4*)(Arow + k);
            As[kpart + 0][lm] = av.x;
            As[kpart + 1][lm] = av.y;
            As[kpart + 2][lm] = av.z;
            As[kpart + 3][lm] = av.w;
        }
        {
            int k = k0 + bkk;
            float4 v = make_float4(0.f, 0.f, 0.f, 0.f);
            if (k < K) v = *(const float4*)(Wm + (size_t)k * GGN + n0 + bn);
            *(float4*)&Bs[bkk][bn] = v;
        }
        __syncthreads();
#pragma unroll
        for (int kk = 0; kk < 8; ++kk) {
            float a[8];
            *(float4*)&a[0] = *(const float4*)&As[kk][ty * 8];
            *(float4*)&a[4] = *(const float4*)&As[kk][ty * 8 + 4];
            float4 b0 = *(const float4*)&Bs[kk][tx * 8];
            float4 b1 = *(const float4*)&Bs[kk][tx * 8 + 4];
            u64 bp[4];
            bp[0] = pack2(b0.x, b0.y); bp[1] = pack2(b0.z, b0.w);
            bp[2] = pack2(b1.x, b1.y); bp[3] = pack2(b1.z, b1.w);
#pragma unroll
            for (int i = 0; i < 8; i++) {
                u64 as = pack2(a[i], a[i]);
#pragma unroll
                for (int j = 0; j < 4; j++) fma2(acc[i][j], as, bp[j]);
            }
        }
        __syncthreads();
    }

#pragma unroll
    for (int i = 0; i < 8; i++) {
        const int m = m0 + ty * 8 + i;
        float* orow = Out + (size_t)m * GGN + n0 + tx * 8;
#pragma unroll
        for (int j = 0; j < 2; j++) {
            float v0, v1, v2, v3;
            unpack2(acc[i][2 * j + 0], v0, v1);
            unpack2(acc[i][2 * j + 1], v2, v3);
            float4 v;
            v.x = v0 + bias[n0 + tx * 8 + j * 4 + 0];
            v.y = v1 + bias[n0 + tx * 8 + j * 4 + 1];
            v.z = v2 + bias[n0 + tx * 8 + j * 4 + 2];
            v.w = v3 + bias[n0 + tx * 8 + j * 4 + 3];
            *(float4*)(orow + j * 4) = v;
        }
    }
}

// ---------------------------------------------------------------------------
// Recurrence v3. Grid: 128 CTAs as 16 clusters of 8, 512 threads/CTA.
//   cluster c: dir = c>>3, batch-group bg = c&7; CTA rank owns 32 units.
// Thread (kg = tid&15, ul = tid>>4): unit ug = rank*32+ul; k-slice =
//   {4*kg + 64*j2 + {0..3}} (quads -> LDS.128); 2 passes of 4 batches,
//   shfl-fold over 16 lanes (4-way dup), h_prev carried in registers.
// Sync: NO cluster barrier in the loop. h broadcast via st.async to each
//   CTA's double-buffered hs + tx-counted mbarrier (8 KB expected/step);
//   consumers try_wait.parity.acquire.cluster. Depth-2 buffering is safe:
//   a CTA's mbar completing for h_{s-1} proves every CTA finished reading
//   h_{s-2}, so overwriting that buffer at step s cannot race.
// ---------------------------------------------------------------------------
__global__ void __cluster_dims__(8, 1, 1) __launch_bounds__(512, 1)
rec_kernel(const float* __restrict__ rkf, const float* __restrict__ rkb,
           const float* __restrict__ biasf, const float* __restrict__ biasb,
           int layer)
{
    __shared__ __align__(16) float hs[2][8][UU];      // 16 KB double buffer
    __shared__ __align__(8)  unsigned long long mb[2]; // tx mbarriers

    const int cta  = blockIdx.x;
    const int rank = cta & 7;
    const int cl   = cta >> 3;
    const int dir  = cl >> 3;
    const int bg   = cl & 7;

    const float* rk   = dir ? rkb   : rkf;
    const float* bias = dir ? biasb : biasf;
    const float* xw   = &g_xw[dir][0][0];

    const int tid = threadIdx.x;
    const int kg  = tid & 15;
    const int ul  = tid >> 4;            // 0..31
    const int ug  = rank * 32 + ul;
    const int bl  = (kg >> 2) & 3;       // fold output batch (pass-local)
    const int b0g = bg * 8 + bl;
    const int b1g = b0g + 4;

    // ---- recurrent weights in registers: pairs j=0..7, k = 4kg + 64*(j>>1) + 2*(j&1)
    u64 rz[8], rr[8], rh[8];
#pragma unroll
    for (int j = 0; j < 8; j++) {
        const int k = 4 * kg + 64 * (j >> 1) + 2 * (j & 1);
        rz[j] = pack2(rk[(size_t)k * GGN + ug],            rk[(size_t)(k + 1) * GGN + ug]);
        rr[j] = pack2(rk[(size_t)k * GGN + UU + ug],       rk[(size_t)(k + 1) * GGN + UU + ug]);
        rh[j] = pack2(rk[(size_t)k * GGN + 2 * UU + ug],   rk[(size_t)(k + 1) * GGN + 2 * UU + ug]);
    }
    const float rbz = bias[GGN + ug];
    const float rbr = bias[GGN + UU + ug];
    const float rbh = bias[GGN + 2 * UU + ug];

    for (int i = tid; i < 2 * 8 * UU; i += 512) ((float*)hs)[i] = 0.f;
    const unsigned hbase = smem_u32(hs);
    const unsigned mbase = smem_u32(mb);
    if (tid == 0) { mbar_init(mbase, 1); mbar_init(mbase + 8, 1); }
    cluster_sync_();   // zeros + mbar init visible cluster-wide

    // ---- remote addresses (buffer 0; parity adds byte offsets) ----
    const int r0 = 2 * (kg & 3), r1 = r0 + 1;
    unsigned dst0[2], dst1[2];
#pragma unroll
    for (int q = 0; q < 2; q++) {
        unsigned local = hbase + (unsigned)(((q * 4 + bl) * UU + ug) * 4);
        dst0[q] = mapa_u32(local, r0);
        dst1[q] = mapa_u32(local, r1);
    }
    const unsigned mb_r0 = mapa_u32(mbase, r0);
    const unsigned mb_r1 = mapa_u32(mbase, r1);

    const float* xr0 = xw + (size_t)b0g * TT * GGN;
    const float* xr1 = xw + (size_t)b1g * TT * GGN;

    int t0 = dir ? TT - 1 : 0;
    float cx[2][3];
    cx[0][0] = xr0[(size_t)t0 * GGN + ug];
    cx[0][1] = xr0[(size_t)t0 * GGN + UU + ug];
    cx[0][2] = xr0[(size_t)t0 * GGN + 2 * UU + ug];
    cx[1][0] = xr1[(size_t)t0 * GGN + ug];
    cx[1][1] = xr1[(size_t)t0 * GGN + UU + ug];
    cx[1][2] = xr1[(size_t)t0 * GGN + 2 * UU + ug];

    float hq[2] = {0.f, 0.f};
    const bool wlane = (kg & 3) == 0;

    int p = 0;            // read buffer for this step
    int par[2] = {0, 0};  // mbar phase parities

    for (int s = 0; s < TT; ++s) {
        const int t = dir ? (TT - 1 - s) : s;
        const int wb = p ^ 1;  // write buffer this step

        // arm this step's write-buffer mbar (safe: its prev phase completed at s-1)
        if (tid == 0 && s < TT - 1) mbar_expect_tx(mbase + 8u * wb, 8 * UU * 4);

        // wait for h_{s-1} (all 8 KB of buffer p delivered)
        if (s > 0) { mbar_wait_cluster(mbase + 8u * p, par[p]); par[p] ^= 1; }

        // prefetch next-step xw
        int tn = dir ? (TT - 2 - s) : (s + 1);
        tn = tn < 0 ? 0 : (tn >= TT ? TT - 1 : tn);
        float nx[2][3];
        nx[0][0] = xr0[(size_t)tn * GGN + ug];
        nx[0][1] = xr0[(size_t)tn * GGN + UU + ug];
        nx[0][2] = xr0[(size_t)tn * GGN + 2 * UU + ug];
        nx[1][0] = xr1[(size_t)tn * GGN + ug];
        nx[1][1] = xr1[(size_t)tn * GGN + UU + ug];
        nx[1][2] = xr1[(size_t)tn * GGN + 2 * UU + ug];

        const float* hc = (const float*)((const char*)hs + p * 8192);
        float hnq[2];

#pragma unroll
        for (int q = 0; q < 2; ++q) {
            u64 az[4], ar4[4], ah4[4];
#pragma unroll
            for (int b = 0; b < 4; b++) { az[b] = 0ull; ar4[b] = 0ull; ah4[b] = 0ull; }

#pragma unroll
            for (int i = 0; i < 4; i++) {
#pragma unroll
                for (int b = 0; b < 4; b++) {
                    const float* hp = hc + (q * 4 + b) * UU + 4 * kg + 64 * i;
                    float4 hv = *(const float4*)hp;      // LDS.128: k..k+3
                    u64 h01 = pack2(hv.x, hv.y);
                    u64 h23 = pack2(hv.z, hv.w);
                    fma2(az[b],  rz[2 * i],     h01);
                    fma2(ar4[b], rr[2 * i],     h01);
                    fma2(ah4[b], rh[2 * i],     h01);
                    fma2(az[b],  rz[2 * i + 1], h23);
                    fma2(ar4[b], rr[2 * i + 1], h23);
                    fma2(ah4[b], rh[2 * i + 1], h23);
                }
            }

            // fold over 16 kg lanes: 4 accs -> 1, then duplicate-sum
            {
                const bool up8 = (kg & 8) != 0;
#pragma unroll
                for (int j = 0; j < 2; j++) {
                    const int keep = up8 ? 2 + j : j;
                    const int send = up8 ? j : 2 + j;
                    az[j]  = add2(az[keep],  shflx64(az[send],  8));
                    ar4[j] = add2(ar4[keep], shflx64(ar4[send], 8));
                    ah4[j] = add2(ah4[keep], shflx64(ah4[send], 8));
                }
                const bool up4 = (kg & 4) != 0;
                const int keep = up4 ? 1 : 0;
                const int send = up4 ? 0 : 1;
                az[0]  = add2(az[keep],  shflx64(az[send],  4));
                ar4[0] = add2(ar4[keep], shflx64(ar4[send], 4));
                ah4[0] = add2(ah4[keep], shflx64(ah4[send], 4));
                az[0]  = add2(az[0],  shflx64(az[0],  2));
                ar4[0] = add2(ar4[0], shflx64(ar4[0], 2));
                ah4[0] = add2(ah4[0], shflx64(ah4[0], 2));
                az[0]  = add2(az[0],  shflx64(az[0],  1));
                ar4[0] = add2(ar4[0], shflx64(ar4[0], 1));
                ah4[0] = add2(ah4[0], shflx64(ah4[0], 1));
            }

            const float rzs  = lohi_sum(az[0])  + rbz;
            const float rrs  = lohi_sum(ar4[0]) + rbr;
            const float rhs_ = lohi_sum(ah4[0]) + rbh;

            const float z  = fast_sigmoid(cx[q][0] + rzs);
            const float r  = fast_sigmoid(cx[q][1] + rrs);
            const float hh = fast_tanh(cx[q][2] + r * rhs_);
            const float hn = z * hq[q] + (1.f - z) * hh;
            hnq[q] = hn;
            hq[q]  = hn;
        }

        // broadcast new h via st.async (skip on last step: nobody waits)
        if (s < TT - 1) {
            const unsigned boff = (unsigned)(wb * 8192);
            const unsigned moff = (unsigned)(8u * wb);
            st_async_f32(dst0[0] + boff, hnq[0], mb_r0 + moff);
            st_async_f32(dst1[0] + boff, hnq[0], mb_r1 + moff);
            st_async_f32(dst0[1] + boff, hnq[1], mb_r0 + moff);
            st_async_f32(dst1[1] + boff, hnq[1], mb_r1 + moff);
        }

        if (layer == 1) {
            if (wlane) {
                g_h1[b0g][t][dir * UU + ug] = hnq[0];
                g_h1[b1g][t][dir * UU + ug] = hnq[1];
            }
        } else if (s == TT - 1) {
            if (wlane) {
                g_h2[b0g][dir * UU + ug] = hnq[0];
                g_h2[b1g][dir * UU + ug] = hnq[1];
            }
        }

#pragma unroll
        for (int q = 0; q < 2; q++)
#pragma unroll
            for (int g = 0; g < 3; g++) cx[q][g] = nx[q][g];
        p ^= 1;
    }

    cluster_sync_();   // keep cluster resident until all traffic quiesces
}

// ---------------------------------------------------------------------------
// Output: softmax(g_h2 @ wout + bout). 64 blocks x 32 threads.
// ---------------------------------------------------------------------------
__global__ __launch_bounds__(32) void out_kernel(
    const float* __restrict__ wout, const float* __restrict__ bout,
    float* __restrict__ out)
{
    __shared__ float h[2 * UU];
    __shared__ float sv[32];
    const int b = blockIdx.x, tid = threadIdx.x;

    for (int i = tid; i < 2 * UU; i += 32) h[i] = g_h2[b][i];
    __syncthreads();

    float s = 0.f;
    if (tid < CC) {
        for (int k = 0; k < 2 * UU; k++) s += h[k] * wout[(size_t)k * CC + tid];
        s += bout[tid];
    }
    sv[tid] = (tid < CC) ? s : -1e30f;
    __syncthreads();

    if (tid < CC) {
        float mx = -1e30f;
        for (int j = 0; j < CC; j++) mx = fmaxf(mx, sv[j]);
        float sum = 0.f;
        for (int j = 0; j < CC; j++) sum += expf(sv[j] - mx);
        out[b * CC + tid] = expf(s - mx) / sum;
    }
}

// ---------------------------------------------------------------------------
// Launch
// ---------------------------------------------------------------------------
extern "C" void kernel_launch(void* const* d_in, const int* in_sizes, int n_in,
                              void* d_out, int out_size) {
    (void)in_sizes; (void)n_in; (void)out_size;
    const int*   x    = (const int*)  d_in[0];
    const float* emb  = (const float*)d_in[1];
    const float* k1f  = (const float*)d_in[2];
    const float* rk1f = (const float*)d_in[3];
    const float* b1f  = (const float*)d_in[4];
    const float* k1b  = (const float*)d_in[5];
    const float* rk1b = (const float*)d_in[6];
    const float* b1b  = (const float*)d_in[7];
    const float* k2f  = (const float*)d_in[8];
    const float* rk2f = (const float*)d_in[9];
    const float* b2f  = (const float*)d_in[10];
    const float* k2b  = (const float*)d_in[11];
    const float* rk2b = (const float*)d_in[12];
    const float* b2b  = (const float*)d_in[13];
    const float* wout = (const float*)d_in[14];
    const float* bout = (const float*)d_in[15];
    float* out = (float*)d_out;

    dim3 pgrid(MM / 128, GGN / 128, 2);

    proj_kernel<<<pgrid, 256>>>(emb, x, k1f, k1b, b1f, b1b, 300, 1);
    rec_kernel<<<128, 512>>>(rk1f, rk1b, b1f, b1b, 1);

    proj_kernel<<<pgrid, 256>>>(emb, x, k2f, k2b, b2f, b2b, 2 * UU, 0);
    rec_kernel<<<128, 512>>>(rk2f, rk2b, b2f, b2b, 2);

    out_kernel<<<VB, 32>>>(wout, bout, out);
}

// round 14
// speedup vs baseline: 1.1113x; 1.0633x over previous
#include <cuda_runtime.h>
#include <cuda_bf16.h>
#include <math.h>

// ---------------------------------------------------------------------------
// Problem dims
// ---------------------------------------------------------------------------
#define VB   64            // batch
#define TT   512           // seq len
#define UU   256           // hidden per direction
#define GGN  768           // 3*U
#define MM   (VB*TT)       // 32768 projection rows
#define CC   20            // classes

// ---------------------------------------------------------------------------
// Scratch (device globals; allocation is forbidden)
// ---------------------------------------------------------------------------
__device__ float g_xw[2][MM][GGN];    // input projections per direction
__device__ float g_h1[VB][TT][2*UU];  // layer-1 output, concat(fwd | bwd)
__device__ float g_h2[VB][2*UU];      // layer-2 final states

// ---------------------------------------------------------------------------
// Helpers
// ---------------------------------------------------------------------------
typedef unsigned long long u64;

__device__ __forceinline__ u64 pack2(float a, float b) {
    u64 r; asm("mov.b64 %0, {%1,%2};" : "=l"(r) : "f"(a), "f"(b)); return r;
}
__device__ __forceinline__ void fma2(u64& d, u64 a, u64 b) {
    asm("fma.rn.f32x2 %0, %1, %2, %0;" : "+l"(d) : "l"(a), "l"(b));
}
__device__ __forceinline__ u64 add2(u64 a, u64 b) {
    u64 r; asm("add.rn.f32x2 %0, %1, %2;" : "=l"(r) : "l"(a), "l"(b)); return r;
}
__device__ __forceinline__ float lohi_sum(u64 v) {
    unsigned lo, hi; asm("mov.b64 {%0,%1}, %2;" : "=r"(lo), "=r"(hi) : "l"(v));
    return __uint_as_float(lo) + __uint_as_float(hi);
}
__device__ __forceinline__ void unpack2(u64 v, float& a, float& b) {
    unsigned lo, hi; asm("mov.b64 {%0,%1}, %2;" : "=r"(lo), "=r"(hi) : "l"(v));
    a = __uint_as_float(lo); b = __uint_as_float(hi);
}
__device__ __forceinline__ u64 shflx64(u64 v, int m) {
    unsigned lo = (unsigned)v, hi = (unsigned)(v >> 32);
    lo = __shfl_xor_sync(0xffffffffu, lo, m);
    hi = __shfl_xor_sync(0xffffffffu, hi, m);
    return ((u64)hi << 32) | (u64)lo;
}
__device__ __forceinline__ unsigned smem_u32(const void* p) {
    unsigned a;
    asm("{ .reg .u64 t; cvta.to.shared.u64 t, %1; cvt.u32.u64 %0, t; }" : "=r"(a) : "l"(p));
    return a;
}
__device__ __forceinline__ unsigned mapa_u32(unsigned addr, int rank) {
    unsigned r;
    asm("mapa.shared::cluster.u32 %0, %1, %2;" : "=r"(r) : "r"(addr), "r"(rank));
    return r;
}
__device__ __forceinline__ void cluster_sync_() {
    asm volatile("barrier.cluster.arrive.aligned;" ::: "memory");
    asm volatile("barrier.cluster.wait.aligned;"   ::: "memory");
}
// Bulk DSMEM copy: src in this CTA's smem -> dst in peer CTA's smem,
// completing `bytes` on the peer's mbarrier.
__device__ __forceinline__ void bulk_dsmem(unsigned dst, unsigned src,
                                           unsigned bytes, unsigned mbar) {
    asm volatile(
        "cp.async.bulk.shared::cluster.shared::cta.mbarrier::complete_tx::bytes "
        "[%0], [%1], %2, [%3];"
        :: "r"(dst), "r"(src), "r"(bytes), "r"(mbar) : "memory");
}
__device__ __forceinline__ void fence_proxy_async_cta() {
    asm volatile("fence.proxy.async.shared::cta;" ::: "memory");
}
__device__ __forceinline__ void mbar_init(unsigned addr, unsigned cnt) {
    asm volatile("mbarrier.init.shared.b64 [%0], %1;" :: "r"(addr), "r"(cnt) : "memory");
}
__device__ __forceinline__ void mbar_expect_tx(unsigned addr, unsigned bytes) {
    asm volatile("mbarrier.arrive.expect_tx.shared.b64 _, [%0], %1;"
                 :: "r"(addr), "r"(bytes) : "memory");
}
__device__ __forceinline__ void mbar_wait(unsigned addr, int parity) {
    asm volatile(
        "{\n\t.reg .pred P;\n\t"
        "LW_%=:\n\t"
        "mbarrier.try_wait.parity.acquire.cta.shared::cta.b64 P, [%0], %1, 0x989680;\n\t"
        "@P bra.uni LD_%=;\n\t"
        "bra.uni LW_%=;\n\t"
        "LD_%=:\n\t}"
        :: "r"(addr), "r"(parity) : "memory");
}
__device__ __forceinline__ float fast_sigmoid(float x) {
    return 1.f / (1.f + __expf(-x));
}
__device__ __forceinline__ float fast_tanh(float x) {
    x = fminf(fmaxf(x, -15.f), 15.f);
    float t = __expf(-2.f * x);
    return (1.f - t) / (1.f + t);
}

// ---------------------------------------------------------------------------
// Projection GEMM: g_xw[dir][m][g] = A[m][:] @ W[:][g] + b0[g]
//   gather==1 (layer 1): A row m = emb[x[m]], K=300
//   gather==0 (layer 2): A row m = g_h1 flat [m][512], K=512
// ---------------------------------------------------------------------------
__global__ __launch_bounds__(256, 2) void proj_kernel(
    const float* __restrict__ emb, const int* __restrict__ xi,
    const float* __restrict__ Wf, const float* __restrict__ Wb,
    const float* __restrict__ bf, const float* __restrict__ bb,
    int K, int gather)
{
    const int dir = blockIdx.z;
    const float* Wm   = dir ? Wb : Wf;
    const float* bias = dir ? bb : bf;
    float* Out = &g_xw[dir][0][0];

    __shared__ float As[8][128];
    __shared__ float Bs[8][128];

    const int tid = threadIdx.x;
    const int m0 = blockIdx.x * 128;
    const int n0 = blockIdx.y * 128;
    const int tx = tid & 15, ty = tid >> 4;

    u64 acc[8][4];
#pragma unroll
    for (int i = 0; i < 8; i++)
#pragma unroll
        for (int j = 0; j < 4; j++) acc[i][j] = 0ull;

    const int lm = tid >> 1;
    const int kpart = (tid & 1) * 4;
    const float* Arow;
    if (gather) Arow = emb + (size_t)xi[m0 + lm] * K;
    else        Arow = &g_h1[0][0][0] + (size_t)(m0 + lm) * K;

    const int bkk = tid >> 5;
    const int bn  = (tid & 31) * 4;

    const int ktiles = (K + 7) / 8;
    for (int kt = 0; kt < ktiles; ++kt) {
        const int k0 = kt * 8;
        {
            int k = k0 + kpart;
            float4 av = make_float4(0.f, 0.f, 0.f, 0.f);
            if (k < K) av = *(const float4*)(Arow + k);
            As[kpart + 0][lm] = av.x;
            As[kpart + 1][lm] = av.y;
            As[kpart + 2][lm] = av.z;
            As[kpart + 3][lm] = av.w;
        }
        {
            int k = k0 + bkk;
            float4 v = make_float4(0.f, 0.f, 0.f, 0.f);
            if (k < K) v = *(const float4*)(Wm + (size_t)k * GGN + n0 + bn);
            *(float4*)&Bs[bkk][bn] = v;
        }
        __syncthreads();
#pragma unroll
        for (int kk = 0; kk < 8; ++kk) {
            float a[8];
            *(float4*)&a[0] = *(const float4*)&As[kk][ty * 8];
            *(float4*)&a[4] = *(const float4*)&As[kk][ty * 8 + 4];
            float4 b0 = *(const float4*)&Bs[kk][tx * 8];
            float4 b1 = *(const float4*)&Bs[kk][tx * 8 + 4];
            u64 bp[4];
            bp[0] = pack2(b0.x, b0.y); bp[1] = pack2(b0.z, b0.w);
            bp[2] = pack2(b1.x, b1.y); bp[3] = pack2(b1.z, b1.w);
#pragma unroll
            for (int i = 0; i < 8; i++) {
                u64 as = pack2(a[i], a[i]);
#pragma unroll
                for (int j = 0; j < 4; j++) fma2(acc[i][j], as, bp[j]);
            }
        }
        __syncthreads();
    }

#pragma unroll
    for (int i = 0; i < 8; i++) {
        const int m = m0 + ty * 8 + i;
        float* orow = Out + (size_t)m * GGN + n0 + tx * 8;
#pragma unroll
        for (int j = 0; j < 2; j++) {
            float v0, v1, v2, v3;
            unpack2(acc[i][2 * j + 0], v0, v1);
            unpack2(acc[i][2 * j + 1], v2, v3);
            float4 v;
            v.x = v0 + bias[n0 + tx * 8 + j * 4 + 0];
            v.y = v1 + bias[n0 + tx * 8 + j * 4 + 1];
            v.z = v2 + bias[n0 + tx * 8 + j * 4 + 2];
            v.w = v3 + bias[n0 + tx * 8 + j * 4 + 3];
            *(float4*)(orow + j * 4) = v;
        }
    }
}

// ---------------------------------------------------------------------------
// Recurrence v4. Grid: 128 CTAs as 16 clusters of 8, 512 threads/CTA.
// h state is SLAB-MAJOR: hs[buf][slab=rank][batch][32 units]. Each CTA's
// per-step contribution is ONE contiguous 1 KB block, broadcast to the 7
// peers with 7 cp.async.bulk DSMEM copies (vs 2048 scalar remote stores in
// v2/v3 — the measured ~18k cyc/step invariant across both scalar protocols).
// Peer receives 7 KB/step counted on a double-buffered tx mbarrier.
// Depth-2 buffer reuse is safe: a peer enters step s only after THIS CTA's
// step s-1 bulk (which follows this CTA's wait + __syncthreads), so no
// write can land in a buffer still being read.
// ---------------------------------------------------------------------------
__global__ void __cluster_dims__(8, 1, 1) __launch_bounds__(512, 1)
rec_kernel(const float* __restrict__ rkf, const float* __restrict__ rkb,
           const float* __restrict__ biasf, const float* __restrict__ biasb,
           int layer)
{
    __shared__ __align__(16) float hs[2][8][8][32];    // [buf][slab][batch][unit] 16KB
    __shared__ __align__(8)  unsigned long long mb[2]; // tx mbarriers

    const int cta  = blockIdx.x;
    const int rank = cta & 7;
    const int cl   = cta >> 3;
    const int dir  = cl >> 3;
    const int bg   = cl & 7;

    const float* rk   = dir ? rkb   : rkf;
    const float* bias = dir ? biasb : biasf;
    const float* xw   = &g_xw[dir][0][0];

    const int tid = threadIdx.x;
    const int kg  = tid & 15;
    const int ul  = tid >> 4;            // 0..31
    const int ug  = rank * 32 + ul;
    const int bl  = (kg >> 2) & 3;       // fold output batch (pass-local)
    const int b0g = bg * 8 + bl;
    const int b1g = b0g + 4;

    // ---- recurrent weights in registers: pairs j=0..7, k = 4kg + 64*(j>>1) + 2*(j&1)
    u64 rz[8], rr[8], rh[8];
#pragma unroll
    for (int j = 0; j < 8; j++) {
        const int k = 4 * kg + 64 * (j >> 1) + 2 * (j & 1);
        rz[j] = pack2(rk[(size_t)k * GGN + ug],            rk[(size_t)(k + 1) * GGN + ug]);
        rr[j] = pack2(rk[(size_t)k * GGN + UU + ug],       rk[(size_t)(k + 1) * GGN + UU + ug]);
        rh[j] = pack2(rk[(size_t)k * GGN + 2 * UU + ug],   rk[(size_t)(k + 1) * GGN + 2 * UU + ug]);
    }
    const float rbz = bias[GGN + ug];
    const float rbr = bias[GGN + UU + ug];
    const float rbh = bias[GGN + 2 * UU + ug];

    for (int i = tid; i < 2 * 8 * 8 * 32; i += 512) ((float*)hs)[i] = 0.f;
    const unsigned hbase = smem_u32(hs);
    const unsigned mbase = smem_u32(mb);
    if (tid == 0) { mbar_init(mbase, 1); mbar_init(mbase + 8, 1); }
    cluster_sync_();   // zeros + mbar init visible cluster-wide

    // ---- bulk-copy plumbing: 7 peers, contiguous 1 KB slab each ----
    const unsigned slab_off = (unsigned)(rank * 1024);
    unsigned bdst = 0, bmb = 0;
    if (tid < 7) {
        const int rd = (rank + 1 + tid) & 7;
        bdst = mapa_u32(hbase + slab_off, rd);   // + wb*8192 at use
        bmb  = mapa_u32(mbase, rd);              // + 8*wb at use
    }

    // consumer read base: slab(kg>>3), offset (kg&7)*16 within [batch][unit] grid
    const unsigned rdoff = (unsigned)(((kg >> 3) * 1024 + (kg & 7) * 16));

    const float* xr0 = xw + (size_t)b0g * TT * GGN;
    const float* xr1 = xw + (size_t)b1g * TT * GGN;

    int t0 = dir ? TT - 1 : 0;
    float cx[2][3];
    cx[0][0] = xr0[(size_t)t0 * GGN + ug];
    cx[0][1] = xr0[(size_t)t0 * GGN + UU + ug];
    cx[0][2] = xr0[(size_t)t0 * GGN + 2 * UU + ug];
    cx[1][0] = xr1[(size_t)t0 * GGN + ug];
    cx[1][1] = xr1[(size_t)t0 * GGN + UU + ug];
    cx[1][2] = xr1[(size_t)t0 * GGN + 2 * UU + ug];

    float hq[2] = {0.f, 0.f};
    const bool wlane = (kg & 3) == 0;
    // own-slab store addresses for wlane threads (q=0: batch bl, q=1: bl+4)
    float* sts0 = &hs[0][rank][bl][ul];
    float* sts1 = &hs[0][rank][bl + 4][ul];

    int p = 0;
    int par[2] = {0, 0};

    for (int s = 0; s < TT; ++s) {
        const int t = dir ? (TT - 1 - s) : s;
        const int wb = p ^ 1;

        // arm this step's write-buffer mbar (7 peers x 1 KB)
        if (tid == 0 && s < TT - 1) mbar_expect_tx(mbase + 8u * wb, 7 * 1024);

        // wait for h_{s-1} (7 KB delivered into buffer p)
        if (s > 0) { mbar_wait(mbase + 8u * p, par[p]); par[p] ^= 1; }

        // prefetch next-step xw
        int tn = dir ? (TT - 2 - s) : (s + 1);
        tn = tn < 0 ? 0 : (tn >= TT ? TT - 1 : tn);
        float nx[2][3];
        nx[0][0] = xr0[(size_t)tn * GGN + ug];
        nx[0][1] = xr0[(size_t)tn * GGN + UU + ug];
        nx[0][2] = xr0[(size_t)tn * GGN + 2 * UU + ug];
        nx[1][0] = xr1[(size_t)tn * GGN + ug];
        nx[1][1] = xr1[(size_t)tn * GGN + UU + ug];
        nx[1][2] = xr1[(size_t)tn * GGN + 2 * UU + ug];

        const char* hc = (const char*)hs + p * 8192 + rdoff;
        float hnq[2];

#pragma unroll
        for (int q = 0; q < 2; ++q) {
            u64 az[4], ar4[4], ah4[4];
#pragma unroll
            for (int b = 0; b < 4; b++) { az[b] = 0ull; ar4[b] = 0ull; ah4[b] = 0ull; }

#pragma unroll
            for (int i = 0; i < 4; i++) {
#pragma unroll
                for (int b = 0; b < 4; b++) {
                    // h[batch = q*4+b][k = 4kg + 64i .. +3] in slab-major layout
                    const float4 hv = *(const float4*)(hc + i * 2048 + (q * 4 + b) * 128);
                    u64 h01 = pack2(hv.x, hv.y);
                    u64 h23 = pack2(hv.z, hv.w);
                    fma2(az[b],  rz[2 * i],     h01);
                    fma2(ar4[b], rr[2 * i],     h01);
                    fma2(ah4[b], rh[2 * i],     h01);
                    fma2(az[b],  rz[2 * i + 1], h23);
                    fma2(ar4[b], rr[2 * i + 1], h23);
                    fma2(ah4[b], rh[2 * i + 1], h23);
                }
            }

            // fold over 16 kg lanes: 4 accs -> 1 (4-way dup result on batch bl)
            {
                const bool up8 = (kg & 8) != 0;
#pragma unroll
                for (int j = 0; j < 2; j++) {
                    const int keep = up8 ? 2 + j : j;
                    const int send = up8 ? j : 2 + j;
                    az[j]  = add2(az[keep],  shflx64(az[send],  8));
                    ar4[j] = add2(ar4[keep], shflx64(ar4[send], 8));
                    ah4[j] = add2(ah4[keep], shflx64(ah4[send], 8));
                }
                const bool up4 = (kg & 4) != 0;
                const int keep = up4 ? 1 : 0;
                const int send = up4 ? 0 : 1;
                az[0]  = add2(az[keep],  shflx64(az[send],  4));
                ar4[0] = add2(ar4[keep], shflx64(ar4[send], 4));
                ah4[0] = add2(ah4[keep], shflx64(ah4[send], 4));
                az[0]  = add2(az[0],  shflx64(az[0],  2));
                ar4[0] = add2(ar4[0], shflx64(ar4[0], 2));
                ah4[0] = add2(ah4[0], shflx64(ah4[0], 2));
                az[0]  = add2(az[0],  shflx64(az[0],  1));
                ar4[0] = add2(ar4[0], shflx64(ar4[0], 1));
                ah4[0] = add2(ah4[0], shflx64(ah4[0], 1));
            }

            const float rzs  = lohi_sum(az[0])  + rbz;
            const float rrs  = lohi_sum(ar4[0]) + rbr;
            const float rhs_ = lohi_sum(ah4[0]) + rbh;

            const float z  = fast_sigmoid(cx[q][0] + rzs);
            const float r  = fast_sigmoid(cx[q][1] + rrs);
            const float hh = fast_tanh(cx[q][2] + r * rhs_);
            const float hn = z * hq[q] + (1.f - z) * hh;
            hnq[q] = hn;
            hq[q]  = hn;
        }

        if (s < TT - 1) {
            // stage own slab locally, then 7 bulk copies broadcast it
            if (wlane) {
                *(float*)((char*)sts0 + wb * 8192) = hnq[0];
                *(float*)((char*)sts1 + wb * 8192) = hnq[1];
            }
            __syncthreads();
            if (tid < 7) {
                fence_proxy_async_cta();
                bulk_dsmem(bdst + (unsigned)(wb * 8192),
                           hbase + (unsigned)(wb * 8192) + slab_off,
                           1024, bmb + (unsigned)(8 * wb));
            }
        }

        if (layer == 1) {
            if (wlane) {
                g_h1[b0g][t][dir * UU + ug] = hnq[0];
                g_h1[b1g][t][dir * UU + ug] = hnq[1];
            }
        } else if (s == TT - 1) {
            if (wlane) {
                g_h2[b0g][dir * UU + ug] = hnq[0];
                g_h2[b1g][dir * UU + ug] = hnq[1];
            }
        }

#pragma unroll
        for (int q = 0; q < 2; q++)
#pragma unroll
            for (int g = 0; g < 3; g++) cx[q][g] = nx[q][g];
        p ^= 1;
    }

    cluster_sync_();   // keep cluster resident until all DSMEM traffic quiesces
}

// ---------------------------------------------------------------------------
// Output: softmax(g_h2 @ wout + bout). 64 blocks x 32 threads.
// ---------------------------------------------------------------------------
__global__ __launch_bounds__(32) void out_kernel(
    const float* __restrict__ wout, const float* __restrict__ bout,
    float* __restrict__ out)
{
    __shared__ float h[2 * UU];
    __shared__ float sv[32];
    const int b = blockIdx.x, tid = threadIdx.x;

    for (int i = tid; i < 2 * UU; i += 32) h[i] = g_h2[b][i];
    __syncthreads();

    float s = 0.f;
    if (tid < CC) {
        for (int k = 0; k < 2 * UU; k++) s += h[k] * wout[(size_t)k * CC + tid];
        s += bout[tid];
    }
    sv[tid] = (tid < CC) ? s : -1e30f;
    __syncthreads();

    if (tid < CC) {
        float mx = -1e30f;
        for (int j = 0; j < CC; j++) mx = fmaxf(mx, sv[j]);
        float sum = 0.f;
        for (int j = 0; j < CC; j++) sum += expf(sv[j] - mx);
        out[b * CC + tid] = expf(s - mx) / sum;
    }
}

// ---------------------------------------------------------------------------
// Launch
// ---------------------------------------------------------------------------
extern "C" void kernel_launch(void* const* d_in, const int* in_sizes, int n_in,
                              void* d_out, int out_size) {
    (void)in_sizes; (void)n_in; (void)out_size;
    const int*   x    = (const int*)  d_in[0];
    const float* emb  = (const float*)d_in[1];
    const float* k1f  = (const float*)d_in[2];
    const float* rk1f = (const float*)d_in[3];
    const float* b1f  = (const float*)d_in[4];
    const float* k1b  = (const float*)d_in[5];
    const float* rk1b = (const float*)d_in[6];
    const float* b1b  = (const float*)d_in[7];
    const float* k2f  = (const float*)d_in[8];
    const float* rk2f = (const float*)d_in[9];
    const float* b2f  = (const float*)d_in[10];
    const float* k2b  = (const float*)d_in[11];
    const float* rk2b = (const float*)d_in[12];
    const float* b2b  = (const float*)d_in[13];
    const float* wout = (const float*)d_in[14];
    const float* bout = (const float*)d_in[15];
    float* out = (float*)d_out;

    dim3 pgrid(MM / 128, GGN / 128, 2);

    proj_kernel<<<pgrid, 256>>>(emb, x, k1f, k1b, b1f, b1b, 300, 1);
    rec_kernel<<<128, 512>>>(rk1f, rk1b, b1f, b1b, 1);

    proj_kernel<<<pgrid, 256>>>(emb, x, k2f, k2b, b2f, b2b, 2 * UU, 0);
    rec_kernel<<<128, 512>>>(rk2f, rk2b, b2f, b2b, 2);

    out_kernel<<<VB, 32>>>(wout, bout, out);
}